// round 15
// baseline (speedup 1.0000x reference)
#include <cuda_runtime.h>
#include <cstdint>

#define BB 32
#define QQ 900
#define CCLS 91
#define TT 30
#define BIGV 1e9f
#define RT 12                          // rows per cost-block (75*12=900)
#define THR 512
#define RTILES (QQ / RT)               // 75

// dynamic SMEM layout (floats):
#define SM_SROW   0                    // RT*QQ tile
#define SM_CLS    (SM_SROW + RT * QQ)  // RT*CCLS focal LUT
#define SM_RB     (SM_CLS + RT * CCLS) // RT float4
#define SM_RX     (SM_RB + RT * 4)
#define SM_RA     (SM_RX + RT * 4)
#define SM_JL     (SM_RA + RT)         // QQ ints (alive list, j-sorted)
#define SM_WC     (SM_JL + QQ)         // 32 ints (per-warp-segment counts)
#define SM_TOTALF (SM_WC + 32)
#define SMEM_BYTES (SM_TOTALF * 4)

// per-row packed pseudo info: keep ? label : -1
__device__ int g_lk[BB * QQ];

__device__ __forceinline__ float frcp_fast(float x) {
    float r;
    asm("rcp.approx.f32 %0, %1;" : "=f"(r) : "f"(x));
    return r;
}

// ---------------------------------------------------------------------------
// Kernel 1: warp-per-row pseudo labels + mask.
// Mask GIoU path uses exact IEEE op order (__f*_rn, no FMA contraction):
// a mask flip swaps ~O(10) values for 1e9 across a whole output column.
// No explicit PDL trigger -> implicit at grid completion (full visibility).
// ---------------------------------------------------------------------------
__global__ void __launch_bounds__(256)
pseudo_kernel(const float* __restrict__ logits_base,
              const float4* __restrict__ boxes_base,
              const float4* __restrict__ targets,
              float* __restrict__ out_mask, int write_mask)
{
    int warp = (blockIdx.x * blockDim.x + threadIdx.x) >> 5;
    int lane = threadIdx.x & 31;
    if (warp >= BB * QQ) return;
    int b = warp / QQ;

    // warp argmax over 91 logits (first-occurrence tie-break)
    const float* row = logits_base + (size_t)warp * CCLS;
    float best = -3.4e38f;
    int bi = 0;
    for (int c = lane; c < CCLS; c += 32) {
        float x = row[c];
        if (x > best) { best = x; bi = c; }
    }
#pragma unroll
    for (int off = 16; off > 0; off >>= 1) {
        float ov = __shfl_down_sync(0xFFFFFFFFu, best, off);
        int   oi = __shfl_down_sync(0xFFFFFFFFu, bi, off);
        if (ov > best || (ov == best && oi < bi)) { best = ov; bi = oi; }
    }
    best = __shfl_sync(0xFFFFFFFFu, best, 0);
    bi   = __shfl_sync(0xFFFFFFFFu, bi, 0);
    int keep = (best > 0.0f);                 // sigmoid(best) > 0.5

    float4 bb = boxes_base[warp];
    float bx0 = __fsub_rn(bb.x, __fmul_rn(0.5f, bb.z));
    float by0 = __fsub_rn(bb.y, __fmul_rn(0.5f, bb.w));
    float bx1 = __fadd_rn(bb.x, __fmul_rn(0.5f, bb.z));
    float by1 = __fadd_rn(bb.y, __fmul_rn(0.5f, bb.w));
    float barea = __fmul_rn(__fsub_rn(bx1, bx0), __fsub_rn(by1, by0));

    int bad = 0;
    if (lane < TT) {
        float4 tb = targets[b * TT + lane];
        float tx0 = __fsub_rn(tb.x, __fmul_rn(0.5f, tb.z));
        float ty0 = __fsub_rn(tb.y, __fmul_rn(0.5f, tb.w));
        float tx1 = __fadd_rn(tb.x, __fmul_rn(0.5f, tb.z));
        float ty1 = __fadd_rn(tb.y, __fmul_rn(0.5f, tb.w));
        float tarea = __fmul_rn(__fsub_rn(tx1, tx0), __fsub_rn(ty1, ty0));

        float lx = fmaxf(bx0, tx0), ly = fmaxf(by0, ty0);
        float rx = fminf(bx1, tx1), ry = fminf(by1, ty1);
        float w = fmaxf(__fsub_rn(rx, lx), 0.0f);
        float h = fmaxf(__fsub_rn(ry, ly), 0.0f);
        float inter = __fmul_rn(w, h);
        float uni = __fsub_rn(__fadd_rn(barea, tarea), inter);
        float iou = __fdiv_rn(inter, uni);

        float clx = fminf(bx0, tx0), cly = fminf(by0, ty0);
        float crx = fmaxf(bx1, tx1), cry = fmaxf(by1, ty1);
        float cw = fmaxf(__fsub_rn(crx, clx), 0.0f);
        float ch = fmaxf(__fsub_rn(cry, cly), 0.0f);
        float ac = __fmul_rn(cw, ch);
        float g = __fsub_rn(iou, __fdiv_rn(__fsub_rn(ac, uni), ac));
        bad = !(-g > -0.1f);
    }
    keep = keep && (__ballot_sync(0xFFFFFFFFu, bad) == 0u);

    if (lane == 0) {
        g_lk[warp] = keep ? bi : -1;
        if (write_mask) out_mask[warp] = keep ? 1.0f : 0.0f;
    }
}

// ---------------------------------------------------------------------------
// Kernel 2: PDL cost kernel. Phase A (row state + LUT + BIG fill) runs
// BEFORE cudaGridDependencySynchronize() -> overlaps pseudo's tail.
// Then: g_lk ballots -> atomic-free j-sorted compaction -> pair loop
// (thread owns alive column, 2 rows share one rcp) -> coalesced writeout.
// RT=12, ~52KB SMEM -> 4 blocks/SM (64 warps).
// ---------------------------------------------------------------------------
__global__ void __launch_bounds__(THR, 4)
cost_kernel(const float4* __restrict__ pred_boxes,
            const float*  __restrict__ pred_logits,
            const float4* __restrict__ boxes_base,
            float* __restrict__ out)
{
    extern __shared__ __align__(16) float sm[];
    float*  srow  = sm + SM_SROW;
    float*  s_cls = sm + SM_CLS;
    float4* s_rb  = (float4*)(sm + SM_RB);
    float4* s_rx  = (float4*)(sm + SM_RX);
    float*  s_ra  = sm + SM_RA;
    int*    s_jl  = (int*)(sm + SM_JL);
    int*    s_wc  = (int*)(sm + SM_WC);

    int b  = blockIdx.y;
    int r0 = blockIdx.x * RT;
    int tid = threadIdx.x;
    int warp = tid >> 5, lane = tid & 31;
    unsigned lmlt = (1u << lane) - 1u;

    // ---- phase A: independent of g_lk ----
    if (tid < RT) {
        float4 pb = __ldg(&pred_boxes[b * QQ + r0 + tid]);
        float hw = 0.5f * pb.z, hh = 0.5f * pb.w;
        float x0 = pb.x - hw, y0 = pb.y - hh;
        float x1 = pb.x + hw, y1 = pb.y + hh;
        s_rb[tid] = pb;
        s_rx[tid] = make_float4(x0, y0, x1, y1);
        s_ra[tid] = (x1 - x0) * (y1 - y0);
    }

    // focal class-cost LUT (fast math)
    for (int idx = tid; idx < RT * CCLS; idx += THR) {
        int r = idx / CCLS, c = idx - r * CCLS;
        float x = __ldg(&pred_logits[(size_t)(b * QQ + r0 + r) * CCLS + c]);
        float e = __expf(-x);
        float p = __fdividef(1.0f, 1.0f + e);
        float omp = 1.0f - p;
        s_cls[idx] = 0.25f * omp * omp * (-__logf(p + 1e-8f))
                   - 0.75f * p * p * (-__logf(omp + 1e-8f));
    }

    // BIG-fill the SMEM tile (flat float4)
    {
        float4* s4 = (float4*)srow;
        const float4 big4 = make_float4(BIGV, BIGV, BIGV, BIGV);
#pragma unroll
        for (int t = tid; t < RT * QQ / 4; t += THR)
            s4[t] = big4;
    }

    // ---- wait for pseudo_kernel's g_lk (PDL) ----
#if __CUDA_ARCH__ >= 900
    cudaGridDependencySynchronize();
#endif

    // alive ballots (2 j-segments: j=tid, j=512+tid)
    int j0 = tid;
    int j1 = 512 + tid;
    int lk0 = __ldg(&g_lk[b * QQ + j0]);
    int lk1 = (j1 < QQ) ? __ldg(&g_lk[b * QQ + j1]) : -1;
    unsigned m0 = __ballot_sync(0xFFFFFFFFu, lk0 >= 0);
    unsigned m1 = __ballot_sync(0xFFFFFFFFu, lk1 >= 0);
    if (lane == 0) {
        s_wc[warp]      = __popc(m0);
        s_wc[16 + warp] = __popc(m1);
    }
    __syncthreads();

    // prefix ranks -> j-sorted alive list
    int nb = 0, base0 = 0, base1 = 0;
#pragma unroll
    for (int k = 0; k < 32; k++) {
        int c = s_wc[k];
        if (k < warp)      base0 += c;
        if (k < 16 + warp) base1 += c;
        nb += c;
    }
    if (lk0 >= 0) s_jl[base0 + __popc(m0 & lmlt)] = j0 | (lk0 << 16);
    if (lk1 >= 0) s_jl[base1 + __popc(m1 & lmlt)] = j1 | (lk1 << 16);
    __syncthreads();

    // ---- pair loop (thread owns one alive column, j-sorted) ----
    if (tid < nb) {
        int jl = s_jl[tid];
        int j = jl & 0xFFFF;
        int lab = jl >> 16;
        float4 jb = __ldg(&boxes_base[b * QQ + j]);   // near-coalesced
        float jhw = 0.5f * jb.z, jhh = 0.5f * jb.w;
        float jx0 = jb.x - jhw, jy0 = jb.y - jhh;
        float jx1 = jb.x + jhw, jy1 = jb.y + jhh;
        float ja  = (jx1 - jx0) * (jy1 - jy0);

#pragma unroll
        for (int r = 0; r < RT; r += 2) {
            // --- row r ---
            float4 rb0 = s_rb[r];
            float4 rx0 = s_rx[r];
            float ra0 = s_ra[r];
            float l1a = fabsf(rb0.x - jb.x) + fabsf(rb0.y - jb.y)
                      + fabsf(rb0.z - jb.z) + fabsf(rb0.w - jb.w);
            float wraw0 = fminf(rx0.z, jx1) - fmaxf(rx0.x, jx0);
            float hraw0 = fminf(rx0.w, jy1) - fmaxf(rx0.y, jy0);
            float w0 = fmaxf(wraw0, 0.0f), h0 = fmaxf(hraw0, 0.0f);
            float inter0 = w0 * h0;
            float uni0 = ra0 + ja - inter0;
            float ac0 = (rb0.z + jb.z - wraw0) * (rb0.w + jb.w - hraw0);
            float num0 = fmaf(inter0 - uni0, ac0, uni0 * uni0);
            float den0 = uni0 * ac0;

            // --- row r+1 ---
            float4 rb1 = s_rb[r + 1];
            float4 rx1 = s_rx[r + 1];
            float ra1 = s_ra[r + 1];
            float l1b = fabsf(rb1.x - jb.x) + fabsf(rb1.y - jb.y)
                      + fabsf(rb1.z - jb.z) + fabsf(rb1.w - jb.w);
            float wraw1 = fminf(rx1.z, jx1) - fmaxf(rx1.x, jx0);
            float hraw1 = fminf(rx1.w, jy1) - fmaxf(rx1.y, jy0);
            float w1 = fmaxf(wraw1, 0.0f), h1 = fmaxf(hraw1, 0.0f);
            float inter1 = w1 * h1;
            float uni1 = ra1 + ja - inter1;
            float ac1 = (rb1.z + jb.z - wraw1) * (rb1.w + jb.w - hraw1);
            float num1 = fmaf(inter1 - uni1, ac1, uni1 * uni1);
            float den1 = uni1 * ac1;

            // one RCP for both rows
            float rp = frcp_fast(den0 * den1);
            float g0 = num0 * (den1 * rp);
            float g1 = num1 * (den0 * rp);

            srow[r * QQ + j] =
                fmaf(2.0f, s_cls[r * CCLS + lab], fmaf(5.0f, l1a, -2.0f * g0));
            srow[(r + 1) * QQ + j] =
                fmaf(2.0f, s_cls[(r + 1) * CCLS + lab], fmaf(5.0f, l1b, -2.0f * g1));
        }
    }
    __syncthreads();

    // ---- coalesced writeout (flat float4) ----
    {
        const float4* s4 = (const float4*)srow;
        const int q4 = QQ / 4;                 // 225
        size_t base = ((size_t)b * QQ + r0) * QQ;
#pragma unroll
        for (int t = tid; t < RT * q4; t += THR) {
            int r = t / q4, c = t - r * q4;
            *(float4*)(out + base + (size_t)r * QQ + c * 4) = s4[t];
        }
    }
}

extern "C" void kernel_launch(void* const* d_in, const int* in_sizes, int n_in,
                              void* d_out, int out_size)
{
    const float*  pred_logits      = (const float*)d_in[0];
    const float4* pred_boxes       = (const float4*)d_in[1];
    const float*  pred_logits_base = (const float*)d_in[2];
    const float4* pred_boxes_base  = (const float4*)d_in[3];
    const float4* targets_boxes    = (const float4*)d_in[4];
    float* out = (float*)d_out;

    const long long c_elems = (long long)BB * QQ * QQ;
    int write_mask = (out_size >= c_elems + BB * QQ) ? 1 : 0;

    cudaFuncSetAttribute(cost_kernel,
                         cudaFuncAttributeMaxDynamicSharedMemorySize,
                         SMEM_BYTES);

    pseudo_kernel<<<(BB * QQ) / 8, 256>>>(
        pred_logits_base, pred_boxes_base, targets_boxes,
        out + c_elems, write_mask);

    // cost kernel launched with PDL so its phase A overlaps pseudo's tail
    cudaLaunchConfig_t cfg = {};
    cfg.gridDim = dim3(RTILES, BB);
    cfg.blockDim = dim3(THR);
    cfg.dynamicSmemBytes = SMEM_BYTES;
    cudaLaunchAttribute attrs[1];
    attrs[0].id = cudaLaunchAttributeProgrammaticStreamSerialization;
    attrs[0].val.programmaticStreamSerializationAllowed = 1;
    cfg.attrs = attrs;
    cfg.numAttrs = 1;
    cudaLaunchKernelEx(&cfg, cost_kernel,
                       pred_boxes, pred_logits, pred_boxes_base, out);
}

// round 16
// speedup vs baseline: 1.0410x; 1.0410x over previous
#include <cuda_runtime.h>
#include <cstdint>

#define BB 32
#define QQ 900
#define CCLS 91
#define TT 30
#define BIGV 1e9f
#define RT 16                          // rows per cost-block
#define THR 512
#define RTILES ((QQ + RT - 1) / RT)    // 57

// dynamic SMEM layout (floats):
#define SM_SROW   0                    // RT*QQ tile
#define SM_CLS    (SM_SROW + RT * QQ)  // RT*CCLS focal LUT
#define SM_RB     (SM_CLS + RT * CCLS) // RT float4
#define SM_RX     (SM_RB + RT * 4)
#define SM_RA     (SM_RX + RT * 4)
#define SM_JL     (SM_RA + RT)         // QQ ints (alive list, j-sorted)
#define SM_WC     (SM_JL + QQ)         // 32 ints (per-warp-segment counts)
#define SM_TOTALF (SM_WC + 32)
#define SMEM_BYTES (SM_TOTALF * 4)

// per-row packed pseudo info: keep ? label : -1
__device__ int g_lk[BB * QQ];

__device__ __forceinline__ float frcp_fast(float x) {
    float r;
    asm("rcp.approx.f32 %0, %1;" : "=f"(r) : "f"(x));
    return r;
}

__device__ __forceinline__ uint32_t smem_u32(const void* p) {
    uint32_t a;
    asm("{ .reg .u64 t; cvta.to.shared.u64 t, %1; cvt.u32.u64 %0, t; }"
        : "=r"(a) : "l"(p));
    return a;
}

// ---------------------------------------------------------------------------
// Kernel 1: warp-per-row pseudo labels + mask.
// Mask GIoU path uses exact IEEE op order (__f*_rn, no FMA contraction):
// a mask flip swaps ~O(10) values for 1e9 across a whole output column.
// ---------------------------------------------------------------------------
__global__ void __launch_bounds__(256)
pseudo_kernel(const float* __restrict__ logits_base,
              const float4* __restrict__ boxes_base,
              const float4* __restrict__ targets,
              float* __restrict__ out_mask, int write_mask)
{
    int warp = (blockIdx.x * blockDim.x + threadIdx.x) >> 5;
    int lane = threadIdx.x & 31;
    if (warp >= BB * QQ) return;
    int b = warp / QQ;

    // warp argmax over 91 logits (first-occurrence tie-break)
    const float* row = logits_base + (size_t)warp * CCLS;
    float best = -3.4e38f;
    int bi = 0;
    for (int c = lane; c < CCLS; c += 32) {
        float x = row[c];
        if (x > best) { best = x; bi = c; }
    }
#pragma unroll
    for (int off = 16; off > 0; off >>= 1) {
        float ov = __shfl_down_sync(0xFFFFFFFFu, best, off);
        int   oi = __shfl_down_sync(0xFFFFFFFFu, bi, off);
        if (ov > best || (ov == best && oi < bi)) { best = ov; bi = oi; }
    }
    best = __shfl_sync(0xFFFFFFFFu, best, 0);
    bi   = __shfl_sync(0xFFFFFFFFu, bi, 0);
    int keep = (best > 0.0f);                 // sigmoid(best) > 0.5

    float4 bb = boxes_base[warp];
    float bx0 = __fsub_rn(bb.x, __fmul_rn(0.5f, bb.z));
    float by0 = __fsub_rn(bb.y, __fmul_rn(0.5f, bb.w));
    float bx1 = __fadd_rn(bb.x, __fmul_rn(0.5f, bb.z));
    float by1 = __fadd_rn(bb.y, __fmul_rn(0.5f, bb.w));
    float barea = __fmul_rn(__fsub_rn(bx1, bx0), __fsub_rn(by1, by0));

    int bad = 0;
    if (lane < TT) {
        float4 tb = targets[b * TT + lane];
        float tx0 = __fsub_rn(tb.x, __fmul_rn(0.5f, tb.z));
        float ty0 = __fsub_rn(tb.y, __fmul_rn(0.5f, tb.w));
        float tx1 = __fadd_rn(tb.x, __fmul_rn(0.5f, tb.z));
        float ty1 = __fadd_rn(tb.y, __fmul_rn(0.5f, tb.w));
        float tarea = __fmul_rn(__fsub_rn(tx1, tx0), __fsub_rn(ty1, ty0));

        float lx = fmaxf(bx0, tx0), ly = fmaxf(by0, ty0);
        float rx = fminf(bx1, tx1), ry = fminf(by1, ty1);
        float w = fmaxf(__fsub_rn(rx, lx), 0.0f);
        float h = fmaxf(__fsub_rn(ry, ly), 0.0f);
        float inter = __fmul_rn(w, h);
        float uni = __fsub_rn(__fadd_rn(barea, tarea), inter);
        float iou = __fdiv_rn(inter, uni);

        float clx = fminf(bx0, tx0), cly = fminf(by0, ty0);
        float crx = fmaxf(bx1, tx1), cry = fmaxf(by1, ty1);
        float cw = fmaxf(__fsub_rn(crx, clx), 0.0f);
        float ch = fmaxf(__fsub_rn(cry, cly), 0.0f);
        float ac = __fmul_rn(cw, ch);
        float g = __fsub_rn(iou, __fdiv_rn(__fsub_rn(ac, uni), ac));
        bad = !(-g > -0.1f);
    }
    keep = keep && (__ballot_sync(0xFFFFFFFFu, bad) == 0u);

    if (lane == 0) {
        g_lk[warp] = keep ? bi : -1;
        if (write_mask) out_mask[warp] = keep ? 1.0f : 0.0f;
    }
}

// ---------------------------------------------------------------------------
// Kernel 2: R14 structure (atomic-free sorted compaction + paired-row RCP)
// with the register writeout replaced by TMA bulk stores (cp.async.bulk):
// 16 threads each issue one 3600B row copy SMEM->GMEM, deleting ~36% of the
// kernel's issued instructions (225 LDS.128 + 225 STG.128 per warp).
// ---------------------------------------------------------------------------
__global__ void __launch_bounds__(THR)
cost_kernel(const float4* __restrict__ pred_boxes,
            const float*  __restrict__ pred_logits,
            const float4* __restrict__ boxes_base,
            float* __restrict__ out)
{
    extern __shared__ __align__(16) float sm[];
    float*  srow  = sm + SM_SROW;
    float*  s_cls = sm + SM_CLS;
    float4* s_rb  = (float4*)(sm + SM_RB);
    float4* s_rx  = (float4*)(sm + SM_RX);
    float*  s_ra  = sm + SM_RA;
    int*    s_jl  = (int*)(sm + SM_JL);
    int*    s_wc  = (int*)(sm + SM_WC);

    int b  = blockIdx.y;
    int r0 = blockIdx.x * RT;
    int nr = min(RT, QQ - r0);              // 16 or 4; always even
    int tid = threadIdx.x;
    int warp = tid >> 5, lane = tid & 31;
    unsigned lmlt = (1u << lane) - 1u;

    // ---- phase A (no internal syncs) ----
    if (tid < nr) {
        float4 pb = __ldg(&pred_boxes[b * QQ + r0 + tid]);
        float hw = 0.5f * pb.z, hh = 0.5f * pb.w;
        float x0 = pb.x - hw, y0 = pb.y - hh;
        float x1 = pb.x + hw, y1 = pb.y + hh;
        s_rb[tid] = pb;
        s_rx[tid] = make_float4(x0, y0, x1, y1);
        s_ra[tid] = (x1 - x0) * (y1 - y0);
    }

    // alive ballots (2 j-segments: j=tid, j=512+tid)
    int j0 = tid;
    int j1 = 512 + tid;
    int lk0 = __ldg(&g_lk[b * QQ + j0]);
    int lk1 = (j1 < QQ) ? __ldg(&g_lk[b * QQ + j1]) : -1;
    unsigned m0 = __ballot_sync(0xFFFFFFFFu, lk0 >= 0);
    unsigned m1 = __ballot_sync(0xFFFFFFFFu, lk1 >= 0);
    if (lane == 0) {
        s_wc[warp]      = __popc(m0);
        s_wc[16 + warp] = __popc(m1);
    }

    // focal class-cost LUT (fast math)
    for (int idx = tid; idx < nr * CCLS; idx += THR) {
        int r = idx / CCLS, c = idx - r * CCLS;
        float x = __ldg(&pred_logits[(size_t)(b * QQ + r0 + r) * CCLS + c]);
        float e = __expf(-x);
        float p = __fdividef(1.0f, 1.0f + e);
        float omp = 1.0f - p;
        s_cls[r * CCLS + c] = 0.25f * omp * omp * (-__logf(p + 1e-8f))
                            - 0.75f * p * p * (-__logf(omp + 1e-8f));
    }

    // BIG-fill the SMEM tile (flat float4)
    {
        float4* s4 = (float4*)srow;
        const float4 big4 = make_float4(BIGV, BIGV, BIGV, BIGV);
#pragma unroll
        for (int t = tid; t < RT * QQ / 4; t += THR)
            s4[t] = big4;
    }
    __syncthreads();

    // ---- phase B: prefix ranks -> j-sorted alive list ----
    int nb = 0, base0 = 0, base1 = 0;
#pragma unroll
    for (int k = 0; k < 32; k++) {
        int c = s_wc[k];
        if (k < warp)      base0 += c;
        if (k < 16 + warp) base1 += c;
        nb += c;
    }
    if (lk0 >= 0) s_jl[base0 + __popc(m0 & lmlt)] = j0 | (lk0 << 16);
    if (lk1 >= 0) s_jl[base1 + __popc(m1 & lmlt)] = j1 | (lk1 << 16);
    __syncthreads();

    // ---- phase C: pair loop (thread owns one alive column, j-sorted) ----
    if (tid < nb) {
        int jl = s_jl[tid];
        int j = jl & 0xFFFF;
        int lab = jl >> 16;
        float4 jb = __ldg(&boxes_base[b * QQ + j]);   // near-coalesced
        float jhw = 0.5f * jb.z, jhh = 0.5f * jb.w;
        float jx0 = jb.x - jhw, jy0 = jb.y - jhh;
        float jx1 = jb.x + jhw, jy1 = jb.y + jhh;
        float ja  = (jx1 - jx0) * (jy1 - jy0);

#pragma unroll
        for (int r = 0; r < RT; r += 2) {
            if (r >= nr) break;
            // --- row r ---
            float4 rb0 = s_rb[r];
            float4 rx0 = s_rx[r];
            float ra0 = s_ra[r];
            float l1a = fabsf(rb0.x - jb.x) + fabsf(rb0.y - jb.y)
                      + fabsf(rb0.z - jb.z) + fabsf(rb0.w - jb.w);
            float wraw0 = fminf(rx0.z, jx1) - fmaxf(rx0.x, jx0);
            float hraw0 = fminf(rx0.w, jy1) - fmaxf(rx0.y, jy0);
            float w0 = fmaxf(wraw0, 0.0f), h0 = fmaxf(hraw0, 0.0f);
            float inter0 = w0 * h0;
            float uni0 = ra0 + ja - inter0;
            float ac0 = (rb0.z + jb.z - wraw0) * (rb0.w + jb.w - hraw0);
            float num0 = fmaf(inter0 - uni0, ac0, uni0 * uni0);
            float den0 = uni0 * ac0;

            // --- row r+1 ---
            float4 rb1 = s_rb[r + 1];
            float4 rx1 = s_rx[r + 1];
            float ra1 = s_ra[r + 1];
            float l1b = fabsf(rb1.x - jb.x) + fabsf(rb1.y - jb.y)
                      + fabsf(rb1.z - jb.z) + fabsf(rb1.w - jb.w);
            float wraw1 = fminf(rx1.z, jx1) - fmaxf(rx1.x, jx0);
            float hraw1 = fminf(rx1.w, jy1) - fmaxf(rx1.y, jy0);
            float w1 = fmaxf(wraw1, 0.0f), h1 = fmaxf(hraw1, 0.0f);
            float inter1 = w1 * h1;
            float uni1 = ra1 + ja - inter1;
            float ac1 = (rb1.z + jb.z - wraw1) * (rb1.w + jb.w - hraw1);
            float num1 = fmaf(inter1 - uni1, ac1, uni1 * uni1);
            float den1 = uni1 * ac1;

            // one RCP for both rows
            float rp = frcp_fast(den0 * den1);
            float g0 = num0 * (den1 * rp);
            float g1 = num1 * (den0 * rp);

            srow[r * QQ + j] =
                fmaf(2.0f, s_cls[r * CCLS + lab], fmaf(5.0f, l1a, -2.0f * g0));
            srow[(r + 1) * QQ + j] =
                fmaf(2.0f, s_cls[(r + 1) * CCLS + lab], fmaf(5.0f, l1b, -2.0f * g1));
        }
    }
    __syncthreads();

    // ---- phase D: TMA bulk writeout (16 threads, one 3600B row each) ----
    asm volatile("fence.proxy.async.shared::cta;" ::: "memory");
    if (tid < nr) {
        uint32_t saddr = smem_u32(srow + tid * QQ);
        const float* gdst = out + ((size_t)b * QQ + r0 + tid) * QQ;
        asm volatile(
            "cp.async.bulk.global.shared::cta.bulk_group [%0], [%1], %2;"
            :: "l"(gdst), "r"(saddr), "r"((int)(QQ * 4)) : "memory");
        asm volatile("cp.async.bulk.commit_group;" ::: "memory");
        asm volatile("cp.async.bulk.wait_group.read 0;" ::: "memory");
    }
    __syncthreads();   // SMEM stays allocated until TMA reads drain
}

extern "C" void kernel_launch(void* const* d_in, const int* in_sizes, int n_in,
                              void* d_out, int out_size)
{
    const float*  pred_logits      = (const float*)d_in[0];
    const float4* pred_boxes       = (const float4*)d_in[1];
    const float*  pred_logits_base = (const float*)d_in[2];
    const float4* pred_boxes_base  = (const float4*)d_in[3];
    const float4* targets_boxes    = (const float4*)d_in[4];
    float* out = (float*)d_out;

    const long long c_elems = (long long)BB * QQ * QQ;
    int write_mask = (out_size >= c_elems + BB * QQ) ? 1 : 0;

    cudaFuncSetAttribute(cost_kernel,
                         cudaFuncAttributeMaxDynamicSharedMemorySize,
                         SMEM_BYTES);

    pseudo_kernel<<<(BB * QQ) / 8, 256>>>(
        pred_logits_base, pred_boxes_base, targets_boxes,
        out + c_elems, write_mask);

    cost_kernel<<<dim3(RTILES, BB), THR, SMEM_BYTES>>>(
        pred_boxes, pred_logits, pred_boxes_base, out);
}

// round 17
// speedup vs baseline: 1.0733x; 1.0311x over previous
#include <cuda_runtime.h>
#include <cstdint>

#define BB 32
#define QQ 900
#define CCLS 91
#define TT 30
#define BIGV 1e9f
#define RT 16                          // rows per cost-block
#define THR 512
#define RTILES ((QQ + RT - 1) / RT)    // 57

// dynamic SMEM layout (floats):
#define SM_SROW   0                    // RT*QQ tile
#define SM_CLS    (SM_SROW + RT * QQ)  // RT*CCLS focal LUT
#define SM_RB     (SM_CLS + RT * CCLS) // RT float4
#define SM_RX     (SM_RB + RT * 4)
#define SM_RA     (SM_RX + RT * 4)
#define SM_JL     (SM_RA + RT)         // QQ ints (alive list, j-sorted)
#define SM_WC     (SM_JL + QQ)         // 32 ints (per-warp-segment counts)
#define SM_TOTALF (SM_WC + 32)
#define SMEM_BYTES (SM_TOTALF * 4)

// per-row packed pseudo info: keep ? label : -1
__device__ int g_lk[BB * QQ];

__device__ __forceinline__ float frcp_fast(float x) {
    float r;
    asm("rcp.approx.f32 %0, %1;" : "=f"(r) : "f"(x));
    return r;
}

__device__ __forceinline__ uint32_t smem_u32(const void* p) {
    uint32_t a;
    asm("{ .reg .u64 t; cvta.to.shared.u64 t, %1; cvt.u32.u64 %0, t; }"
        : "=r"(a) : "l"(p));
    return a;
}

// ---------------------------------------------------------------------------
// Kernel 1: warp-per-row pseudo labels + mask.
// Mask GIoU path uses exact IEEE op order (__f*_rn, no FMA contraction):
// a mask flip swaps ~O(10) values for 1e9 across a whole output column.
// Implicit PDL trigger at grid completion -> full g_lk visibility.
// ---------------------------------------------------------------------------
__global__ void __launch_bounds__(256)
pseudo_kernel(const float* __restrict__ logits_base,
              const float4* __restrict__ boxes_base,
              const float4* __restrict__ targets,
              float* __restrict__ out_mask, int write_mask)
{
    int warp = (blockIdx.x * blockDim.x + threadIdx.x) >> 5;
    int lane = threadIdx.x & 31;
    if (warp >= BB * QQ) return;
    int b = warp / QQ;

    // warp argmax over 91 logits (first-occurrence tie-break)
    const float* row = logits_base + (size_t)warp * CCLS;
    float best = -3.4e38f;
    int bi = 0;
    for (int c = lane; c < CCLS; c += 32) {
        float x = row[c];
        if (x > best) { best = x; bi = c; }
    }
#pragma unroll
    for (int off = 16; off > 0; off >>= 1) {
        float ov = __shfl_down_sync(0xFFFFFFFFu, best, off);
        int   oi = __shfl_down_sync(0xFFFFFFFFu, bi, off);
        if (ov > best || (ov == best && oi < bi)) { best = ov; bi = oi; }
    }
    best = __shfl_sync(0xFFFFFFFFu, best, 0);
    bi   = __shfl_sync(0xFFFFFFFFu, bi, 0);
    int keep = (best > 0.0f);                 // sigmoid(best) > 0.5

    float4 bb = boxes_base[warp];
    float bx0 = __fsub_rn(bb.x, __fmul_rn(0.5f, bb.z));
    float by0 = __fsub_rn(bb.y, __fmul_rn(0.5f, bb.w));
    float bx1 = __fadd_rn(bb.x, __fmul_rn(0.5f, bb.z));
    float by1 = __fadd_rn(bb.y, __fmul_rn(0.5f, bb.w));
    float barea = __fmul_rn(__fsub_rn(bx1, bx0), __fsub_rn(by1, by0));

    int bad = 0;
    if (lane < TT) {
        float4 tb = targets[b * TT + lane];
        float tx0 = __fsub_rn(tb.x, __fmul_rn(0.5f, tb.z));
        float ty0 = __fsub_rn(tb.y, __fmul_rn(0.5f, tb.w));
        float tx1 = __fadd_rn(tb.x, __fmul_rn(0.5f, tb.z));
        float ty1 = __fadd_rn(tb.y, __fmul_rn(0.5f, tb.w));
        float tarea = __fmul_rn(__fsub_rn(tx1, tx0), __fsub_rn(ty1, ty0));

        float lx = fmaxf(bx0, tx0), ly = fmaxf(by0, ty0);
        float rx = fminf(bx1, tx1), ry = fminf(by1, ty1);
        float w = fmaxf(__fsub_rn(rx, lx), 0.0f);
        float h = fmaxf(__fsub_rn(ry, ly), 0.0f);
        float inter = __fmul_rn(w, h);
        float uni = __fsub_rn(__fadd_rn(barea, tarea), inter);
        float iou = __fdiv_rn(inter, uni);

        float clx = fminf(bx0, tx0), cly = fminf(by0, ty0);
        float crx = fmaxf(bx1, tx1), cry = fmaxf(by1, ty1);
        float cw = fmaxf(__fsub_rn(crx, clx), 0.0f);
        float ch = fmaxf(__fsub_rn(cry, cly), 0.0f);
        float ac = __fmul_rn(cw, ch);
        float g = __fsub_rn(iou, __fdiv_rn(__fsub_rn(ac, uni), ac));
        bad = !(-g > -0.1f);
    }
    keep = keep && (__ballot_sync(0xFFFFFFFFu, bad) == 0u);

    if (lane == 0) {
        g_lk[warp] = keep ? bi : -1;
        if (write_mask) out_mask[warp] = keep ? 1.0f : 0.0f;
    }
}

// ---------------------------------------------------------------------------
// Kernel 2: R16 cost kernel + PDL. Phase A (row state + LUT + BIG fill,
// independent of g_lk) runs BEFORE cudaGridDependencySynchronize() and
// overlaps pseudo's tail + launch gap. Then: alive ballots -> atomic-free
// j-sorted compaction -> pair loop (2 rows share one rcp) -> TMA writeout.
// ---------------------------------------------------------------------------
__global__ void __launch_bounds__(THR)
cost_kernel(const float4* __restrict__ pred_boxes,
            const float*  __restrict__ pred_logits,
            const float4* __restrict__ boxes_base,
            float* __restrict__ out)
{
    extern __shared__ __align__(16) float sm[];
    float*  srow  = sm + SM_SROW;
    float*  s_cls = sm + SM_CLS;
    float4* s_rb  = (float4*)(sm + SM_RB);
    float4* s_rx  = (float4*)(sm + SM_RX);
    float*  s_ra  = sm + SM_RA;
    int*    s_jl  = (int*)(sm + SM_JL);
    int*    s_wc  = (int*)(sm + SM_WC);

    int b  = blockIdx.y;
    int r0 = blockIdx.x * RT;
    int nr = min(RT, QQ - r0);              // 16 or 4; always even
    int tid = threadIdx.x;
    int warp = tid >> 5, lane = tid & 31;
    unsigned lmlt = (1u << lane) - 1u;

    // ---- phase A: independent of g_lk (overlaps pseudo via PDL) ----
    if (tid < nr) {
        float4 pb = __ldg(&pred_boxes[b * QQ + r0 + tid]);
        float hw = 0.5f * pb.z, hh = 0.5f * pb.w;
        float x0 = pb.x - hw, y0 = pb.y - hh;
        float x1 = pb.x + hw, y1 = pb.y + hh;
        s_rb[tid] = pb;
        s_rx[tid] = make_float4(x0, y0, x1, y1);
        s_ra[tid] = (x1 - x0) * (y1 - y0);
    }

    // focal class-cost LUT (fast math)
    for (int idx = tid; idx < nr * CCLS; idx += THR) {
        int r = idx / CCLS, c = idx - r * CCLS;
        float x = __ldg(&pred_logits[(size_t)(b * QQ + r0 + r) * CCLS + c]);
        float e = __expf(-x);
        float p = __fdividef(1.0f, 1.0f + e);
        float omp = 1.0f - p;
        s_cls[r * CCLS + c] = 0.25f * omp * omp * (-__logf(p + 1e-8f))
                            - 0.75f * p * p * (-__logf(omp + 1e-8f));
    }

    // BIG-fill the SMEM tile (flat float4)
    {
        float4* s4 = (float4*)srow;
        const float4 big4 = make_float4(BIGV, BIGV, BIGV, BIGV);
#pragma unroll
        for (int t = tid; t < RT * QQ / 4; t += THR)
            s4[t] = big4;
    }

    // ---- wait for pseudo_kernel's g_lk (PDL) ----
#if __CUDA_ARCH__ >= 900
    cudaGridDependencySynchronize();
#endif

    // alive ballots (2 j-segments: j=tid, j=512+tid)
    int j0 = tid;
    int j1 = 512 + tid;
    int lk0 = __ldg(&g_lk[b * QQ + j0]);
    int lk1 = (j1 < QQ) ? __ldg(&g_lk[b * QQ + j1]) : -1;
    unsigned m0 = __ballot_sync(0xFFFFFFFFu, lk0 >= 0);
    unsigned m1 = __ballot_sync(0xFFFFFFFFu, lk1 >= 0);
    if (lane == 0) {
        s_wc[warp]      = __popc(m0);
        s_wc[16 + warp] = __popc(m1);
    }
    __syncthreads();

    // prefix ranks -> j-sorted alive list
    int nb = 0, base0 = 0, base1 = 0;
#pragma unroll
    for (int k = 0; k < 32; k++) {
        int c = s_wc[k];
        if (k < warp)      base0 += c;
        if (k < 16 + warp) base1 += c;
        nb += c;
    }
    if (lk0 >= 0) s_jl[base0 + __popc(m0 & lmlt)] = j0 | (lk0 << 16);
    if (lk1 >= 0) s_jl[base1 + __popc(m1 & lmlt)] = j1 | (lk1 << 16);
    __syncthreads();

    // ---- pair loop (thread owns one alive column, j-sorted) ----
    if (tid < nb) {
        int jl = s_jl[tid];
        int j = jl & 0xFFFF;
        int lab = jl >> 16;
        float4 jb = __ldg(&boxes_base[b * QQ + j]);   // near-coalesced
        float jhw = 0.5f * jb.z, jhh = 0.5f * jb.w;
        float jx0 = jb.x - jhw, jy0 = jb.y - jhh;
        float jx1 = jb.x + jhw, jy1 = jb.y + jhh;
        float ja  = (jx1 - jx0) * (jy1 - jy0);

#pragma unroll
        for (int r = 0; r < RT; r += 2) {
            if (r >= nr) break;
            // --- row r ---
            float4 rb0 = s_rb[r];
            float4 rx0 = s_rx[r];
            float ra0 = s_ra[r];
            float l1a = fabsf(rb0.x - jb.x) + fabsf(rb0.y - jb.y)
                      + fabsf(rb0.z - jb.z) + fabsf(rb0.w - jb.w);
            float wraw0 = fminf(rx0.z, jx1) - fmaxf(rx0.x, jx0);
            float hraw0 = fminf(rx0.w, jy1) - fmaxf(rx0.y, jy0);
            float w0 = fmaxf(wraw0, 0.0f), h0 = fmaxf(hraw0, 0.0f);
            float inter0 = w0 * h0;
            float uni0 = ra0 + ja - inter0;
            float ac0 = (rb0.z + jb.z - wraw0) * (rb0.w + jb.w - hraw0);
            float num0 = fmaf(inter0 - uni0, ac0, uni0 * uni0);
            float den0 = uni0 * ac0;

            // --- row r+1 ---
            float4 rb1 = s_rb[r + 1];
            float4 rx1 = s_rx[r + 1];
            float ra1 = s_ra[r + 1];
            float l1b = fabsf(rb1.x - jb.x) + fabsf(rb1.y - jb.y)
                      + fabsf(rb1.z - jb.z) + fabsf(rb1.w - jb.w);
            float wraw1 = fminf(rx1.z, jx1) - fmaxf(rx1.x, jx0);
            float hraw1 = fminf(rx1.w, jy1) - fmaxf(rx1.y, jy0);
            float w1 = fmaxf(wraw1, 0.0f), h1 = fmaxf(hraw1, 0.0f);
            float inter1 = w1 * h1;
            float uni1 = ra1 + ja - inter1;
            float ac1 = (rb1.z + jb.z - wraw1) * (rb1.w + jb.w - hraw1);
            float num1 = fmaf(inter1 - uni1, ac1, uni1 * uni1);
            float den1 = uni1 * ac1;

            // one RCP for both rows
            float rp = frcp_fast(den0 * den1);
            float g0 = num0 * (den1 * rp);
            float g1 = num1 * (den0 * rp);

            srow[r * QQ + j] =
                fmaf(2.0f, s_cls[r * CCLS + lab], fmaf(5.0f, l1a, -2.0f * g0));
            srow[(r + 1) * QQ + j] =
                fmaf(2.0f, s_cls[(r + 1) * CCLS + lab], fmaf(5.0f, l1b, -2.0f * g1));
        }
    }
    __syncthreads();

    // ---- TMA bulk writeout (nr threads, one 3600B row each) ----
    asm volatile("fence.proxy.async.shared::cta;" ::: "memory");
    if (tid < nr) {
        uint32_t saddr = smem_u32(srow + tid * QQ);
        const float* gdst = out + ((size_t)b * QQ + r0 + tid) * QQ;
        asm volatile(
            "cp.async.bulk.global.shared::cta.bulk_group [%0], [%1], %2;"
            :: "l"(gdst), "r"(saddr), "r"((int)(QQ * 4)) : "memory");
        asm volatile("cp.async.bulk.commit_group;" ::: "memory");
        asm volatile("cp.async.bulk.wait_group.read 0;" ::: "memory");
    }
    __syncthreads();   // SMEM stays allocated until TMA reads drain
}

extern "C" void kernel_launch(void* const* d_in, const int* in_sizes, int n_in,
                              void* d_out, int out_size)
{
    const float*  pred_logits      = (const float*)d_in[0];
    const float4* pred_boxes       = (const float4*)d_in[1];
    const float*  pred_logits_base = (const float*)d_in[2];
    const float4* pred_boxes_base  = (const float4*)d_in[3];
    const float4* targets_boxes    = (const float4*)d_in[4];
    float* out = (float*)d_out;

    const long long c_elems = (long long)BB * QQ * QQ;
    int write_mask = (out_size >= c_elems + BB * QQ) ? 1 : 0;

    cudaFuncSetAttribute(cost_kernel,
                         cudaFuncAttributeMaxDynamicSharedMemorySize,
                         SMEM_BYTES);

    pseudo_kernel<<<(BB * QQ) / 8, 256>>>(
        pred_logits_base, pred_boxes_base, targets_boxes,
        out + c_elems, write_mask);

    // PDL launch: cost kernel's phase A overlaps pseudo's execution
    cudaLaunchConfig_t cfg = {};
    cfg.gridDim = dim3(RTILES, BB);
    cfg.blockDim = dim3(THR);
    cfg.dynamicSmemBytes = SMEM_BYTES;
    cudaLaunchAttribute attrs[1];
    attrs[0].id = cudaLaunchAttributeProgrammaticStreamSerialization;
    attrs[0].val.programmaticStreamSerializationAllowed = 1;
    cfg.attrs = attrs;
    cfg.numAttrs = 1;
    cudaLaunchKernelEx(&cfg, cost_kernel,
                       pred_boxes, pred_logits, pred_boxes_base, out);
}